// round 15
// baseline (speedup 1.0000x reference)
#include <cuda_runtime.h>
#include <cuda_fp16.h>
#include <cstdint>

// ---------------------------------------------------------------------------
// Problem dims
// ---------------------------------------------------------------------------
#define BB   256
#define TT   128
#define CC   512
#define HID  1024
#define HOR  96
#define MM   (BB * TT)          // 32768
#define KROW 1024               // stored row length: [hi | lo] halves
#define KCH  24                 // logical K chunks of 64 halves (K_ext = 1536)
#define TIL_M 128               // = one batch (TT rows)
#define TIL_N 128
#define NSTG 2                  // 2 slots -> 64KB/CTA -> 3 CTAs/SM
#define A_STG_BYTES 16384       // 128 rows x 128B
#define B_STG_BYTES 16384       // 128 rows x 128B
#define STAGE_BYTES (A_STG_BYTES + B_STG_BYTES)        // 32KB
#define SMEM_TOTAL  (NSTG * STAGE_BYTES)               // 64KB/CTA
#define NT   128                // threads per CTA (4 warps, 2x2 warp grid)

// ---------------------------------------------------------------------------
// Scratch (__device__ globals: allocation-free rule)
// ---------------------------------------------------------------------------
__device__ __half g_Aext[(size_t)MM * KROW];    // 64 MB  [ah | al]
__device__ __half g_Bext[(size_t)HID * KROW];   //  2 MB  [bh | bl]
__device__ float  g_mem[(size_t)BB * HID];      //  1 MB

// Logical chunk -> stored column offset (halves).
// A sequence: ah(0..7), ah(0..7), al(0..7)   B sequence: bh, bl, bh
__device__ __forceinline__ int ofsA(int kc) {
    return (kc < 16) ? (kc & 7) * 64 : 512 + (kc & 7) * 64;
}
__device__ __forceinline__ int ofsB(int kc) {
    return (kc < 8) ? kc * 64 : ((kc < 16) ? 512 + (kc & 7) * 64 : (kc & 7) * 64);
}

// ---------------------------------------------------------------------------
// Baseline-PTX helpers (sm_80-level: valid on .target sm_103)
// ---------------------------------------------------------------------------
__device__ __forceinline__ uint32_t smem_u32_of(const void* p) {
    uint32_t a;
    asm("{ .reg .u64 t; cvta.to.shared.u64 t, %1; cvt.u32.u64 %0, t; }"
        : "=r"(a) : "l"(p));
    return a;
}
__device__ __forceinline__ void cp16(uint32_t dst, const void* src) {
    asm volatile("cp.async.cg.shared.global [%0], [%1], 16;"
                 :: "r"(dst), "l"(src) : "memory");
}
__device__ __forceinline__ void cp_commit() {
    asm volatile("cp.async.commit_group;" ::: "memory");
}
__device__ __forceinline__ void ldsm4(uint32_t* r, uint32_t addr) {
    asm volatile("ldmatrix.sync.aligned.m8n8.x4.shared.b16 {%0,%1,%2,%3}, [%4];"
                 : "=r"(r[0]), "=r"(r[1]), "=r"(r[2]), "=r"(r[3]) : "r"(addr));
}
__device__ __forceinline__ void mma16816(float* c, const uint32_t* a,
                                         uint32_t b0, uint32_t b1) {
    asm volatile(
        "mma.sync.aligned.m16n8k16.row.col.f32.f16.f16.f32 "
        "{%0,%1,%2,%3}, {%4,%5,%6,%7}, {%8,%9}, {%0,%1,%2,%3};"
        : "+f"(c[0]), "+f"(c[1]), "+f"(c[2]), "+f"(c[3])
        : "r"(a[0]), "r"(a[1]), "r"(a[2]), "r"(a[3]), "r"(b0), "r"(b1));
}

// ---------------------------------------------------------------------------
// fp16 split pack helpers
// ---------------------------------------------------------------------------
__device__ __forceinline__ uint2 pack4(__half a, __half b, __half c, __half d) {
    __half2 p0 = __halves2half2(a, b);
    __half2 p1 = __halves2half2(c, d);
    uint2 u;
    u.x = *reinterpret_cast<uint32_t*>(&p0);
    u.y = *reinterpret_cast<uint32_t*>(&p1);
    return u;
}
__device__ __forceinline__ void split1(float f, __half& hi, __half& lo) {
    hi = __float2half_rn(f);
    lo = __float2half_rn(f - __half2float(hi));
}

// ---------------------------------------------------------------------------
// Kernel 0a: x [MM,CC] f32 -> g_Aext [MM, 1024] = [ah | al]
// ---------------------------------------------------------------------------
__global__ __launch_bounds__(256) void convert_x_kernel(const float* __restrict__ x)
{
    const int i = blockIdx.x * 256 + threadIdx.x;   // one float4 group
    const float4 v = reinterpret_cast<const float4*>(x)[i];
    const int m  = i >> 7;          // CC/4 = 128 groups per row
    const int k4 = i & 127;
    __half h0, h1, h2, h3, l0, l1, l2, l3;
    split1(v.x, h0, l0); split1(v.y, h1, l1);
    split1(v.z, h2, l2); split1(v.w, h3, l3);
    uint2* dst = reinterpret_cast<uint2*>(g_Aext + (size_t)m * KROW);
    dst[k4]       = pack4(h0, h1, h2, h3);   // cols   0- 511: ah
    dst[128 + k4] = pack4(l0, l1, l2, l3);   // cols 512-1023: al
}

// Kernel 0b: W1 [HID,CC] f32 -> g_Bext [HID, 1024] = [bh | bl]
__global__ __launch_bounds__(256) void convert_w_kernel(const float* __restrict__ w)
{
    const int i = blockIdx.x * 256 + threadIdx.x;   // < HID*CC/4 = 131072
    const float4 v = reinterpret_cast<const float4*>(w)[i];
    const int n  = i >> 7;
    const int k4 = i & 127;
    __half h0, h1, h2, h3, l0, l1, l2, l3;
    split1(v.x, h0, l0); split1(v.y, h1, l1);
    split1(v.z, h2, l2); split1(v.w, h3, l3);
    uint2* dst = reinterpret_cast<uint2*>(g_Bext + (size_t)n * KROW);
    dst[k4]       = pack4(h0, h1, h2, h3);   // bh
    dst[128 + k4] = pack4(l0, l1, l2, l3);   // bl
}

// ---------------------------------------------------------------------------
// Kernel 1: HMMA GEMM 128x128 per CTA, 128 threads (4 warps, warp tile
// 64x64), 3 CTAs/SM (12 warps/SM, 3 independent barrier domains).
// 2-slot cp.async pipeline, depth-1 prefetch; ldsm addresses precomputed;
// stage offsets are literals. Accumulation order identical to prior rounds.
// ---------------------------------------------------------------------------
__device__ __forceinline__ void load_stage(uint32_t smem_base, int s, int kc,
                                           int bm, int bn, int tid)
{
    const uint32_t sa = smem_base + s * STAGE_BYTES;
    const uint32_t sb = sa + A_STG_BYTES;
    const __half* ga = g_Aext + (size_t)bm * KROW + ofsA(kc);
    const __half* gb = g_Bext + (size_t)bn * KROW + ofsB(kc);
    // A: 128 rows x 8 chunks of 16B -> 1024 chunks, 8 per thread (128 thr)
#pragma unroll
    for (int j = 0; j < 8; j++) {
        const int idx = tid + j * NT;
        const int r = idx >> 3;
        const int c = idx & 7;
        uint32_t off = r * 128 + c * 16;
        off ^= (off >> 3) & 0x70;
        cp16(sa + off, ga + (size_t)r * KROW + c * 8);
    }
    // B: 128 rows x 8 chunks -> 1024 chunks, 8 per thread
#pragma unroll
    for (int j = 0; j < 8; j++) {
        const int idx = tid + j * NT;
        const int r = idx >> 3;
        const int c = idx & 7;
        uint32_t off = r * 128 + c * 16;
        off ^= (off >> 3) & 0x70;
        cp16(sb + off, gb + (size_t)r * KROW + c * 8);
    }
}

// One 64-half chunk of MMAs from stage at literal byte offset SOFF.
#define COMPUTE_CHUNK(SOFF)                                                   \
    do {                                                                      \
        _Pragma("unroll")                                                     \
        for (int ks = 0; ks < 4; ks++) {                                      \
            uint32_t af[4][4], bf[4][4];                                      \
            _Pragma("unroll")                                                 \
            for (int i = 0; i < 4; i++) ldsm4(af[i], aA[i * 4 + ks] + (SOFF));\
            _Pragma("unroll")                                                 \
            for (int j = 0; j < 4; j++) ldsm4(bf[j], aB[j * 4 + ks] + (SOFF));\
            _Pragma("unroll")                                                 \
            for (int i = 0; i < 4; i++)                                       \
                _Pragma("unroll")                                             \
                for (int j = 0; j < 4; j++) {                                 \
                    mma16816(c[i][2 * j],     af[i], bf[j][0], bf[j][2]);     \
                    mma16816(c[i][2 * j + 1], af[i], bf[j][1], bf[j][3]);     \
                }                                                             \
        }                                                                     \
    } while (0)

#define WAIT0 asm volatile("cp.async.wait_group 0;" ::: "memory")

__global__ __launch_bounds__(NT, 3) void gemm_scan_kernel(
    const float* __restrict__ b1, const float* __restrict__ beta_p)
{
    extern __shared__ char smem[];
    const uint32_t smem_base = smem_u32_of(smem);
    const int tid  = threadIdx.x;
    const int lane = tid & 31;
    const int wid  = tid >> 5;
    const int wm   = wid >> 1;      // 0..1 : warp row (64 M each)
    const int wn   = wid & 1;       // 0..1 : warp col (64 N each)
    const int bm = blockIdx.y * TIL_M;
    const int bn = blockIdx.x * TIL_N;

    float c[4][8][4];               // warp tile 64x64: 4 m16 x 8 n8 frags
#pragma unroll
    for (int i = 0; i < 4; i++)
#pragma unroll
        for (int j = 0; j < 8; j++)
#pragma unroll
            for (int q = 0; q < 4; q++) c[i][j][q] = 0.0f;

    // Precompute all swizzled ldsm addresses for slot 0 (32 registers).
    // Swizzle XOR mask depends only on the row (bits >=7), so these are
    // loop-invariant; slot 1 adds the literal STAGE_BYTES.
    uint32_t aA[16], aB[16];
    {
        const uint32_t l16 = (uint32_t)((lane >> 4) << 4);
#pragma unroll
        for (int i = 0; i < 4; i++) {
            const uint32_t row = wm * 64 + i * 16 + (lane & 15);
#pragma unroll
            for (int ks = 0; ks < 4; ks++) {
                uint32_t off = row * 128 + ks * 32 + l16;
                off ^= (off >> 3) & 0x70;
                aA[i * 4 + ks] = smem_base + off;
            }
        }
#pragma unroll
        for (int j = 0; j < 4; j++) {
            const uint32_t row = wn * 64 + j * 16 + (lane & 15);
#pragma unroll
            for (int ks = 0; ks < 4; ks++) {
                uint32_t off = row * 128 + ks * 32 + l16;
                off ^= (off >> 3) & 0x70;
                aB[j * 4 + ks] = smem_base + A_STG_BYTES + off;
            }
        }
    }

    // prologue: chunk 0 -> slot 0
    load_stage(smem_base, 0, 0, bm, bn, tid);
    cp_commit();

    // 12 groups of 2 chunks; slot = kc & 1 as literal offsets
    for (int g = 0; g < 12; g++) {
        const int kcb = g * 2;
        // kc = kcb (slot 0); prefetch kcb+1 -> slot 1
        WAIT0; __syncthreads();
        load_stage(smem_base, 1, kcb + 1, bm, bn, tid); cp_commit();
        COMPUTE_CHUNK(0);
        // kc = kcb+1 (slot 1); prefetch kcb+2 -> slot 0
        WAIT0; __syncthreads();
        if (g < 11) { load_stage(smem_base, 0, kcb + 2, bm, bn, tid); cp_commit(); }
        COMPUTE_CHUNK(STAGE_BYTES);
    }
    __syncthreads();   // all compute done before smem is reused as fp32 buffer

    // ------- fused epilogue + scan, two t-phases ([64][129] = 33KB) -------
    float* sf = reinterpret_cast<float*>(smem);
    const float beta_c = fminf(fmaxf(beta_p[0], 0.0f), 1.0f);
    const float bias_h = b1[bn + tid];
    float mem = 0.0f;

    // phase 0: rows 0..63 (held by wm==0 warps)
    if (wm == 0) {
#pragma unroll
        for (int i = 0; i < 4; i++) {
            const int r0 = i * 16 + (lane >> 2);            // 0..63
#pragma unroll
            for (int j = 0; j < 8; j++) {
                const int col = wn * 64 + j * 8 + ((lane & 3) << 1);
                sf[r0 * 129 + col]           = c[i][j][0];
                sf[r0 * 129 + col + 1]       = c[i][j][1];
                sf[(r0 + 8) * 129 + col]     = c[i][j][2];
                sf[(r0 + 8) * 129 + col + 1] = c[i][j][3];
            }
        }
    }
    __syncthreads();
#pragma unroll 8
    for (int t = 0; t < 64; t++) {
        const float inp   = sf[t * 129 + tid] + bias_h;
        const float reset = (mem > 1.0f) ? 1.0f : 0.0f;     // THR = 1.0
        mem = fmaf(beta_c, mem, inp - reset);
    }
    __syncthreads();

    // phase 1: rows 64..127 (held by wm==1 warps), stored at buffer rows 0..63
    if (wm == 1) {
#pragma unroll
        for (int i = 0; i < 4; i++) {
            const int r0 = i * 16 + (lane >> 2);            // buffer row
#pragma unroll
            for (int j = 0; j < 8; j++) {
                const int col = wn * 64 + j * 8 + ((lane & 3) << 1);
                sf[r0 * 129 + col]           = c[i][j][0];
                sf[r0 * 129 + col + 1]       = c[i][j][1];
                sf[(r0 + 8) * 129 + col]     = c[i][j][2];
                sf[(r0 + 8) * 129 + col + 1] = c[i][j][3];
            }
        }
    }
    __syncthreads();
#pragma unroll 8
    for (int t = 0; t < 64; t++) {
        const float inp   = sf[t * 129 + tid] + bias_h;
        const float reset = (mem > 1.0f) ? 1.0f : 0.0f;
        mem = fmaf(beta_c, mem, inp - reset);
    }
    g_mem[(size_t)blockIdx.y * HID + bn + tid] = mem;
}

// ---------------------------------------------------------------------------
// Kernel 2: head GEMM  out[b][o] = g_mem[b] . Wh[o] + bh[o]
// grid (BB, 4): 24 outputs per block (best measured config, 12.9us).
// ---------------------------------------------------------------------------
__global__ __launch_bounds__(256) void head_kernel(
    const float* __restrict__ Wh, const float* __restrict__ bh,
    float* __restrict__ out)
{
    __shared__ float s_mem[HID];
    const int b  = blockIdx.x;
    const int os = blockIdx.y * 24;           // output range [os, os+24)

    for (int i = threadIdx.x; i < HID; i += 256)
        s_mem[i] = g_mem[(size_t)b * HID + i];
    __syncthreads();

    const int warp = threadIdx.x >> 5;
    const int lane = threadIdx.x & 31;

    for (int o = os + warp; o < os + 24; o += 8) {
        const float4* w = reinterpret_cast<const float4*>(Wh + (size_t)o * HID);
        float acc = 0.0f;
#pragma unroll
        for (int h = lane; h < HID / 4; h += 32) {
            const float4 wv = w[h];
            const float4 mv = *reinterpret_cast<const float4*>(s_mem + h * 4);
            acc = fmaf(wv.x, mv.x, acc);
            acc = fmaf(wv.y, mv.y, acc);
            acc = fmaf(wv.z, mv.z, acc);
            acc = fmaf(wv.w, mv.w, acc);
        }
#pragma unroll
        for (int off = 16; off > 0; off >>= 1)
            acc += __shfl_xor_sync(0xFFFFFFFFu, acc, off);
        if (lane == 0) out[(size_t)b * HOR + o] = acc + bh[o];
    }
}

// ---------------------------------------------------------------------------
extern "C" void kernel_launch(void* const* d_in, const int* in_sizes, int n_in,
                              void* d_out, int out_size)
{
    const float* x    = (const float*)d_in[0];  // [B,T,C]
    const float* W1   = (const float*)d_in[1];  // [HID,C]
    const float* b1   = (const float*)d_in[2];  // [HID]
    const float* Wh   = (const float*)d_in[3];  // [HOR,HID]
    const float* bh   = (const float*)d_in[4];  // [HOR]
    const float* beta = (const float*)d_in[5];  // scalar
    float* out = (float*)d_out;                 // [B,HOR]

    cudaFuncSetAttribute(gemm_scan_kernel,
                         cudaFuncAttributeMaxDynamicSharedMemorySize, SMEM_TOTAL);

    convert_x_kernel<<<(MM * CC / 4) / 256, 256>>>(x);
    convert_w_kernel<<<(HID * CC / 4) / 256, 256>>>(W1);

    dim3 grid(HID / TIL_N, MM / TIL_M);   // (8, 256) = 2048 CTAs
    gemm_scan_kernel<<<grid, NT, SMEM_TOTAL>>>(b1, beta);

    dim3 hgrid(BB, 4);                    // 1024 blocks
    head_kernel<<<hgrid, 256>>>(Wh, bh, out);
}

// round 16
// speedup vs baseline: 1.2456x; 1.2456x over previous
#include <cuda_runtime.h>
#include <cuda_fp16.h>
#include <cstdint>

// ---------------------------------------------------------------------------
// Problem dims
// ---------------------------------------------------------------------------
#define BB   256
#define TT   128
#define CC   512
#define HID  1024
#define HOR  96
#define MM   (BB * TT)          // 32768
#define KROW 1024               // stored row length: [hi | lo] halves
#define KCH  24                 // logical K chunks of 64 halves (K_ext = 1536)
#define TIL_M 128               // = one batch (TT rows)
#define TIL_N 128
#define NSTG 3
#define A_STG_BYTES 16384       // 128 rows x 128B
#define B_STG_BYTES 16384       // 128 rows x 128B
#define STAGE_BYTES (A_STG_BYTES + B_STG_BYTES)        // 32KB
#define SMEM_TOTAL  (NSTG * STAGE_BYTES)               // 96KB/CTA, 2 CTAs/SM
#define NT   128                // threads per CTA (4 warps, 2x2 warp grid)

// ---------------------------------------------------------------------------
// Scratch (__device__ globals: allocation-free rule)
// ---------------------------------------------------------------------------
__device__ __half g_Aext[(size_t)MM * KROW];    // 64 MB  [ah | al]
__device__ __half g_Bext[(size_t)HID * KROW];   //  2 MB  [bh | bl]
__device__ float  g_mem[(size_t)BB * HID];      //  1 MB

// Logical chunk -> stored column offset (halves).
// A sequence: ah(0..7), ah(0..7), al(0..7)   B sequence: bh, bl, bh
__device__ __forceinline__ int ofsA(int kc) {
    return (kc < 16) ? (kc & 7) * 64 : 512 + (kc & 7) * 64;
}
__device__ __forceinline__ int ofsB(int kc) {
    return (kc < 8) ? kc * 64 : ((kc < 16) ? 512 + (kc & 7) * 64 : (kc & 7) * 64);
}

// ---------------------------------------------------------------------------
// Baseline-PTX helpers (sm_80-level: valid on .target sm_103)
// ---------------------------------------------------------------------------
__device__ __forceinline__ uint32_t smem_u32_of(const void* p) {
    uint32_t a;
    asm("{ .reg .u64 t; cvta.to.shared.u64 t, %1; cvt.u32.u64 %0, t; }"
        : "=r"(a) : "l"(p));
    return a;
}
__device__ __forceinline__ void cp16(uint32_t dst, const void* src) {
    asm volatile("cp.async.cg.shared.global [%0], [%1], 16;"
                 :: "r"(dst), "l"(src) : "memory");
}
__device__ __forceinline__ void cp_commit() {
    asm volatile("cp.async.commit_group;" ::: "memory");
}
__device__ __forceinline__ void ldsm4(uint32_t* r, uint32_t addr) {
    asm volatile("ldmatrix.sync.aligned.m8n8.x4.shared.b16 {%0,%1,%2,%3}, [%4];"
                 : "=r"(r[0]), "=r"(r[1]), "=r"(r[2]), "=r"(r[3]) : "r"(addr));
}
__device__ __forceinline__ void mma16816(float* c, const uint32_t* a,
                                         uint32_t b0, uint32_t b1) {
    asm volatile(
        "mma.sync.aligned.m16n8k16.row.col.f32.f16.f16.f32 "
        "{%0,%1,%2,%3}, {%4,%5,%6,%7}, {%8,%9}, {%0,%1,%2,%3};"
        : "+f"(c[0]), "+f"(c[1]), "+f"(c[2]), "+f"(c[3])
        : "r"(a[0]), "r"(a[1]), "r"(a[2]), "r"(a[3]), "r"(b0), "r"(b1));
}

// ---------------------------------------------------------------------------
// fp16 split pack helpers
// ---------------------------------------------------------------------------
__device__ __forceinline__ uint2 pack4(__half a, __half b, __half c, __half d) {
    __half2 p0 = __halves2half2(a, b);
    __half2 p1 = __halves2half2(c, d);
    uint2 u;
    u.x = *reinterpret_cast<uint32_t*>(&p0);
    u.y = *reinterpret_cast<uint32_t*>(&p1);
    return u;
}
__device__ __forceinline__ void split1(float f, __half& hi, __half& lo) {
    hi = __float2half_rn(f);
    lo = __float2half_rn(f - __half2float(hi));
}

// ---------------------------------------------------------------------------
// Kernel 0a: x [MM,CC] f32 -> g_Aext [MM, 1024] = [ah | al]
// ---------------------------------------------------------------------------
__global__ __launch_bounds__(256) void convert_x_kernel(const float* __restrict__ x)
{
    const int i = blockIdx.x * 256 + threadIdx.x;   // one float4 group
    const float4 v = reinterpret_cast<const float4*>(x)[i];
    const int m  = i >> 7;          // CC/4 = 128 groups per row
    const int k4 = i & 127;
    __half h0, h1, h2, h3, l0, l1, l2, l3;
    split1(v.x, h0, l0); split1(v.y, h1, l1);
    split1(v.z, h2, l2); split1(v.w, h3, l3);
    uint2* dst = reinterpret_cast<uint2*>(g_Aext + (size_t)m * KROW);
    dst[k4]       = pack4(h0, h1, h2, h3);   // cols   0- 511: ah
    dst[128 + k4] = pack4(l0, l1, l2, l3);   // cols 512-1023: al
}

// Kernel 0b: W1 [HID,CC] f32 -> g_Bext [HID, 1024] = [bh | bl]
__global__ __launch_bounds__(256) void convert_w_kernel(const float* __restrict__ w)
{
    const int i = blockIdx.x * 256 + threadIdx.x;   // < HID*CC/4 = 131072
    const float4 v = reinterpret_cast<const float4*>(w)[i];
    const int n  = i >> 7;
    const int k4 = i & 127;
    __half h0, h1, h2, h3, l0, l1, l2, l3;
    split1(v.x, h0, l0); split1(v.y, h1, l1);
    split1(v.z, h2, l2); split1(v.w, h3, l3);
    uint2* dst = reinterpret_cast<uint2*>(g_Bext + (size_t)n * KROW);
    dst[k4]       = pack4(h0, h1, h2, h3);   // bh
    dst[128 + k4] = pack4(l0, l1, l2, l3);   // bl
}

// ---------------------------------------------------------------------------
// Kernel 1 (R14 config — best measured): HMMA GEMM 128x128 per CTA,
// 128 threads (4 warps, warp tile 64x64), 2 CTAs/SM, 256-reg cap (no spill).
// 3-slot cp.async pipeline, depth-2 prefetch, precomputed ldsm addresses,
// stage rotation fully unrolled (literal offsets).
// ---------------------------------------------------------------------------
__device__ __forceinline__ void load_stage(uint32_t smem_base, int s, int kc,
                                           int bm, int bn, int tid)
{
    const uint32_t sa = smem_base + s * STAGE_BYTES;
    const uint32_t sb = sa + A_STG_BYTES;
    const __half* ga = g_Aext + (size_t)bm * KROW + ofsA(kc);
    const __half* gb = g_Bext + (size_t)bn * KROW + ofsB(kc);
    // A: 128 rows x 8 chunks of 16B -> 1024 chunks, 8 per thread (128 thr)
#pragma unroll
    for (int j = 0; j < 8; j++) {
        const int idx = tid + j * NT;
        const int r = idx >> 3;
        const int c = idx & 7;
        uint32_t off = r * 128 + c * 16;
        off ^= (off >> 3) & 0x70;
        cp16(sa + off, ga + (size_t)r * KROW + c * 8);
    }
    // B: 128 rows x 8 chunks -> 1024 chunks, 8 per thread
#pragma unroll
    for (int j = 0; j < 8; j++) {
        const int idx = tid + j * NT;
        const int r = idx >> 3;
        const int c = idx & 7;
        uint32_t off = r * 128 + c * 16;
        off ^= (off >> 3) & 0x70;
        cp16(sb + off, gb + (size_t)r * KROW + c * 8);
    }
}

// One 64-half chunk of MMAs from stage at literal byte offset SOFF.
#define COMPUTE_CHUNK(SOFF)                                                   \
    do {                                                                      \
        _Pragma("unroll")                                                     \
        for (int ks = 0; ks < 4; ks++) {                                      \
            uint32_t af[4][4], bf[4][4];                                      \
            _Pragma("unroll")                                                 \
            for (int i = 0; i < 4; i++) ldsm4(af[i], aA[i * 4 + ks] + (SOFF));\
            _Pragma("unroll")                                                 \
            for (int j = 0; j < 4; j++) ldsm4(bf[j], aB[j * 4 + ks] + (SOFF));\
            _Pragma("unroll")                                                 \
            for (int i = 0; i < 4; i++)                                       \
                _Pragma("unroll")                                             \
                for (int j = 0; j < 4; j++) {                                 \
                    mma16816(c[i][2 * j],     af[i], bf[j][0], bf[j][2]);     \
                    mma16816(c[i][2 * j + 1], af[i], bf[j][1], bf[j][3]);     \
                }                                                             \
        }                                                                     \
    } while (0)

#define WAIT1 asm volatile("cp.async.wait_group 1;" ::: "memory")
#define WAIT0 asm volatile("cp.async.wait_group 0;" ::: "memory")

__global__ __launch_bounds__(NT, 2) void gemm_scan_kernel(
    const float* __restrict__ b1, const float* __restrict__ beta_p)
{
    extern __shared__ char smem[];
    const uint32_t smem_base = smem_u32_of(smem);
    const int tid  = threadIdx.x;
    const int lane = tid & 31;
    const int wid  = tid >> 5;
    const int wm   = wid >> 1;      // 0..1 : warp row (64 M each)
    const int wn   = wid & 1;       // 0..1 : warp col (64 N each)
    const int bm = blockIdx.y * TIL_M;
    const int bn = blockIdx.x * TIL_N;

    float c[4][8][4];               // warp tile 64x64: 4 m16 x 8 n8 frags
#pragma unroll
    for (int i = 0; i < 4; i++)
#pragma unroll
        for (int j = 0; j < 8; j++)
#pragma unroll
            for (int q = 0; q < 4; q++) c[i][j][q] = 0.0f;

    // Precompute all swizzled ldsm addresses for stage 0 (32 registers).
    // The swizzle XOR mask depends only on the row (bits >=7 of off), so
    // these are loop-invariant; other stages add a literal offset.
    uint32_t aA[16], aB[16];
    {
        const uint32_t l16 = (uint32_t)((lane >> 4) << 4);
#pragma unroll
        for (int i = 0; i < 4; i++) {
            const uint32_t row = wm * 64 + i * 16 + (lane & 15);
#pragma unroll
            for (int ks = 0; ks < 4; ks++) {
                uint32_t off = row * 128 + ks * 32 + l16;
                off ^= (off >> 3) & 0x70;
                aA[i * 4 + ks] = smem_base + off;
            }
        }
#pragma unroll
        for (int j = 0; j < 4; j++) {
            const uint32_t row = wn * 64 + j * 16 + (lane & 15);
#pragma unroll
            for (int ks = 0; ks < 4; ks++) {
                uint32_t off = row * 128 + ks * 32 + l16;
                off ^= (off >> 3) & 0x70;
                aB[j * 4 + ks] = smem_base + A_STG_BYTES + off;
            }
        }
    }

    // prologue: fill slots 0..1 (depth-2 prefetch)
    load_stage(smem_base, 0, 0, bm, bn, tid);
    cp_commit();
    load_stage(smem_base, 1, 1, bm, bn, tid);
    cp_commit();

    // full-rate phase: kc = 0..20 as 7 groups of 3 (slot = kc % 3 literal)
    for (int g = 0; g < 7; g++) {
        const int kcb = g * 3;
        // kc = kcb, slot 0; prefetch kcb+2 -> slot 2
        WAIT1; __syncthreads();
        load_stage(smem_base, 2, kcb + 2, bm, bn, tid); cp_commit();
        COMPUTE_CHUNK(0);
        // kc = kcb+1, slot 1; prefetch kcb+3 -> slot 0
        WAIT1; __syncthreads();
        load_stage(smem_base, 0, kcb + 3, bm, bn, tid); cp_commit();
        COMPUTE_CHUNK(STAGE_BYTES);
        // kc = kcb+2, slot 2; prefetch kcb+4 -> slot 1
        WAIT1; __syncthreads();
        load_stage(smem_base, 1, kcb + 4, bm, bn, tid); cp_commit();
        COMPUTE_CHUNK(2 * STAGE_BYTES);
    }
    // kc = 21 (slot 0): prefetch 23 -> slot 2
    WAIT1; __syncthreads();
    load_stage(smem_base, 2, 23, bm, bn, tid); cp_commit();
    COMPUTE_CHUNK(0);
    // kc = 22 (slot 1): no prefetch
    WAIT1; __syncthreads();
    COMPUTE_CHUNK(STAGE_BYTES);
    // kc = 23 (slot 2)
    WAIT0; __syncthreads();
    COMPUTE_CHUNK(2 * STAGE_BYTES);

    __syncthreads();   // all compute done before smem is reused as fp32 buffer

    // ------------------ fused epilogue + scan ------------------
    float* sf = reinterpret_cast<float*>(smem);   // [128][129] fp32 = 66KB
#pragma unroll
    for (int i = 0; i < 4; i++) {
        const int r0 = wm * 64 + i * 16 + (lane >> 2);
#pragma unroll
        for (int j = 0; j < 8; j++) {
            const int col = wn * 64 + j * 8 + ((lane & 3) << 1);
            sf[r0 * 129 + col]           = c[i][j][0];
            sf[r0 * 129 + col + 1]       = c[i][j][1];
            sf[(r0 + 8) * 129 + col]     = c[i][j][2];
            sf[(r0 + 8) * 129 + col + 1] = c[i][j][3];
        }
    }
    __syncthreads();

    {
        const float beta_c = fminf(fmaxf(beta_p[0], 0.0f), 1.0f);
        const float bias_h = b1[bn + tid];
        float mem = 0.0f;
#pragma unroll 8
        for (int t = 0; t < TT; t++) {
            const float inp   = sf[t * 129 + tid] + bias_h;
            const float reset = (mem > 1.0f) ? 1.0f : 0.0f;   // THR = 1.0
            mem = fmaf(beta_c, mem, inp - reset);
        }
        g_mem[(size_t)blockIdx.y * HID + bn + tid] = mem;
    }
}

// ---------------------------------------------------------------------------
// Kernel 2 (R10 config — best measured, 12.9us): head GEMM
// out[b][o] = g_mem[b] . Wh[o] + bh[o]; grid (BB, 4), 24 outputs per block.
// ---------------------------------------------------------------------------
__global__ __launch_bounds__(256) void head_kernel(
    const float* __restrict__ Wh, const float* __restrict__ bh,
    float* __restrict__ out)
{
    __shared__ float s_mem[HID];
    const int b  = blockIdx.x;
    const int os = blockIdx.y * 24;           // output range [os, os+24)

    for (int i = threadIdx.x; i < HID; i += 256)
        s_mem[i] = g_mem[(size_t)b * HID + i];
    __syncthreads();

    const int warp = threadIdx.x >> 5;
    const int lane = threadIdx.x & 31;

    for (int o = os + warp; o < os + 24; o += 8) {
        const float4* w = reinterpret_cast<const float4*>(Wh + (size_t)o * HID);
        float acc = 0.0f;
#pragma unroll
        for (int h = lane; h < HID / 4; h += 32) {
            const float4 wv = w[h];
            const float4 mv = *reinterpret_cast<const float4*>(s_mem + h * 4);
            acc = fmaf(wv.x, mv.x, acc);
            acc = fmaf(wv.y, mv.y, acc);
            acc = fmaf(wv.z, mv.z, acc);
            acc = fmaf(wv.w, mv.w, acc);
        }
#pragma unroll
        for (int off = 16; off > 0; off >>= 1)
            acc += __shfl_xor_sync(0xFFFFFFFFu, acc, off);
        if (lane == 0) out[(size_t)b * HOR + o] = acc + bh[o];
    }
}

// ---------------------------------------------------------------------------
extern "C" void kernel_launch(void* const* d_in, const int* in_sizes, int n_in,
                              void* d_out, int out_size)
{
    const float* x    = (const float*)d_in[0];  // [B,T,C]
    const float* W1   = (const float*)d_in[1];  // [HID,C]
    const float* b1   = (const float*)d_in[2];  // [HID]
    const float* Wh   = (const float*)d_in[3];  // [HOR,HID]
    const float* bh   = (const float*)d_in[4];  // [HOR]
    const float* beta = (const float*)d_in[5];  // scalar
    float* out = (float*)d_out;                 // [B,HOR]

    cudaFuncSetAttribute(gemm_scan_kernel,
                         cudaFuncAttributeMaxDynamicSharedMemorySize, SMEM_TOTAL);

    convert_x_kernel<<<(MM * CC / 4) / 256, 256>>>(x);
    convert_w_kernel<<<(HID * CC / 4) / 256, 256>>>(W1);

    dim3 grid(HID / TIL_N, MM / TIL_M);   // (8, 256) = 2048 CTAs
    gemm_scan_kernel<<<grid, NT, SMEM_TOTAL>>>(b1, beta);

    dim3 hgrid(BB, 4);                    // 1024 blocks
    head_kernel<<<hgrid, 256>>>(Wh, bh, out);
}

// round 17
// speedup vs baseline: 1.2504x; 1.0038x over previous
#include <cuda_runtime.h>
#include <cuda_fp16.h>
#include <cstdint>

// ---------------------------------------------------------------------------
// Problem dims
// ---------------------------------------------------------------------------
#define BB   256
#define TT   128
#define CC   512
#define HID  1024
#define HOR  96
#define MM   (BB * TT)          // 32768
#define KROW 1024               // stored row length: [hi | lo] halves
#define KCH  24                 // logical K chunks of 64 halves (K_ext = 1536)
#define TIL_M 128               // = one batch (TT rows)
#define TIL_N 128
#define NSTG 3
#define A_STG_BYTES 16384       // 128 rows x 128B
#define B_STG_BYTES 16384       // 128 rows x 128B
#define STAGE_BYTES (A_STG_BYTES + B_STG_BYTES)        // 32KB
#define SMEM_TOTAL  (NSTG * STAGE_BYTES)               // 96KB/CTA, 2 CTAs/SM
#define NT   128                // threads per CTA (4 warps, 2x2 warp grid)

// ---------------------------------------------------------------------------
// Scratch (__device__ globals: allocation-free rule)
// ---------------------------------------------------------------------------
__device__ __half g_Aext[(size_t)MM * KROW];    // 64 MB  [ah | al]
__device__ __half g_Bext[(size_t)HID * KROW];   //  2 MB  [bh | bl]
__device__ float  g_mem[(size_t)BB * HID];      //  1 MB

// Logical chunk -> stored column offset (halves).
// A sequence: ah(0..7), ah(0..7), al(0..7)   B sequence: bh, bl, bh
__device__ __forceinline__ int ofsA(int kc) {
    return (kc < 16) ? (kc & 7) * 64 : 512 + (kc & 7) * 64;
}
__device__ __forceinline__ int ofsB(int kc) {
    return (kc < 8) ? kc * 64 : ((kc < 16) ? 512 + (kc & 7) * 64 : (kc & 7) * 64);
}

// ---------------------------------------------------------------------------
// Baseline-PTX helpers (sm_80-level: valid on .target sm_103)
// ---------------------------------------------------------------------------
__device__ __forceinline__ uint32_t smem_u32_of(const void* p) {
    uint32_t a;
    asm("{ .reg .u64 t; cvta.to.shared.u64 t, %1; cvt.u32.u64 %0, t; }"
        : "=r"(a) : "l"(p));
    return a;
}
__device__ __forceinline__ void cp16(uint32_t dst, const void* src) {
    asm volatile("cp.async.cg.shared.global [%0], [%1], 16;"
                 :: "r"(dst), "l"(src) : "memory");
}
__device__ __forceinline__ void cp_commit() {
    asm volatile("cp.async.commit_group;" ::: "memory");
}
__device__ __forceinline__ void ldsm4(uint32_t* r, uint32_t addr) {
    asm volatile("ldmatrix.sync.aligned.m8n8.x4.shared.b16 {%0,%1,%2,%3}, [%4];"
                 : "=r"(r[0]), "=r"(r[1]), "=r"(r[2]), "=r"(r[3]) : "r"(addr));
}
__device__ __forceinline__ void mma16816(float* c, const uint32_t* a,
                                         uint32_t b0, uint32_t b1) {
    asm volatile(
        "mma.sync.aligned.m16n8k16.row.col.f32.f16.f16.f32 "
        "{%0,%1,%2,%3}, {%4,%5,%6,%7}, {%8,%9}, {%0,%1,%2,%3};"
        : "+f"(c[0]), "+f"(c[1]), "+f"(c[2]), "+f"(c[3])
        : "r"(a[0]), "r"(a[1]), "r"(a[2]), "r"(a[3]), "r"(b0), "r"(b1));
}

// ---------------------------------------------------------------------------
// fp16 split pack helpers
// ---------------------------------------------------------------------------
__device__ __forceinline__ uint2 pack4(__half a, __half b, __half c, __half d) {
    __half2 p0 = __halves2half2(a, b);
    __half2 p1 = __halves2half2(c, d);
    uint2 u;
    u.x = *reinterpret_cast<uint32_t*>(&p0);
    u.y = *reinterpret_cast<uint32_t*>(&p1);
    return u;
}
__device__ __forceinline__ void split1(float f, __half& hi, __half& lo) {
    hi = __float2half_rn(f);
    lo = __float2half_rn(f - __half2float(hi));
}

// ---------------------------------------------------------------------------
// Kernel 0 (merged): blocks [0, 16384): x -> g_Aext ; [16384, 16896): W1 -> g_Bext
// Per-element code byte-identical to the previous separate kernels.
// ---------------------------------------------------------------------------
#define XBLKS (MM * CC / 4 / 256)     // 16384
__global__ __launch_bounds__(256) void convert_kernel(
    const float* __restrict__ x, const float* __restrict__ w)
{
    if (blockIdx.x < XBLKS) {
        const int i = blockIdx.x * 256 + threadIdx.x;   // one float4 group
        const float4 v = reinterpret_cast<const float4*>(x)[i];
        const int m  = i >> 7;          // CC/4 = 128 groups per row
        const int k4 = i & 127;
        __half h0, h1, h2, h3, l0, l1, l2, l3;
        split1(v.x, h0, l0); split1(v.y, h1, l1);
        split1(v.z, h2, l2); split1(v.w, h3, l3);
        uint2* dst = reinterpret_cast<uint2*>(g_Aext + (size_t)m * KROW);
        dst[k4]       = pack4(h0, h1, h2, h3);   // cols   0- 511: ah
        dst[128 + k4] = pack4(l0, l1, l2, l3);   // cols 512-1023: al
    } else {
        const int i = (blockIdx.x - XBLKS) * 256 + threadIdx.x;  // < 131072
        const float4 v = reinterpret_cast<const float4*>(w)[i];
        const int n  = i >> 7;
        const int k4 = i & 127;
        __half h0, h1, h2, h3, l0, l1, l2, l3;
        split1(v.x, h0, l0); split1(v.y, h1, l1);
        split1(v.z, h2, l2); split1(v.w, h3, l3);
        uint2* dst = reinterpret_cast<uint2*>(g_Bext + (size_t)n * KROW);
        dst[k4]       = pack4(h0, h1, h2, h3);   // bh
        dst[128 + k4] = pack4(l0, l1, l2, l3);   // bl
    }
}

// ---------------------------------------------------------------------------
// Kernel 1: HMMA GEMM 128x128 per CTA, 128 threads (4 warps, warp tile
// 64x64), 2 CTAs/SM, 256-reg cap. 3-slot cp.async pipeline, depth-2
// prefetch, precomputed ldsm addresses, literal stage offsets, and
// ks-level fragment double-buffering (loads of ks+1 overlap MMAs of ks).
// MMA order per element unchanged -> identical numerics.
// ---------------------------------------------------------------------------
__device__ __forceinline__ void load_stage(uint32_t smem_base, int s, int kc,
                                           int bm, int bn, int tid)
{
    const uint32_t sa = smem_base + s * STAGE_BYTES;
    const uint32_t sb = sa + A_STG_BYTES;
    const __half* ga = g_Aext + (size_t)bm * KROW + ofsA(kc);
    const __half* gb = g_Bext + (size_t)bn * KROW + ofsB(kc);
    // A: 128 rows x 8 chunks of 16B -> 1024 chunks, 8 per thread (128 thr)
#pragma unroll
    for (int j = 0; j < 8; j++) {
        const int idx = tid + j * NT;
        const int r = idx >> 3;
        const int c = idx & 7;
        uint32_t off = r * 128 + c * 16;
        off ^= (off >> 3) & 0x70;
        cp16(sa + off, ga + (size_t)r * KROW + c * 8);
    }
    // B: 128 rows x 8 chunks -> 1024 chunks, 8 per thread
#pragma unroll
    for (int j = 0; j < 8; j++) {
        const int idx = tid + j * NT;
        const int r = idx >> 3;
        const int c = idx & 7;
        uint32_t off = r * 128 + c * 16;
        off ^= (off >> 3) & 0x70;
        cp16(sb + off, gb + (size_t)r * KROW + c * 8);
    }
}

// Load the 8 fragments of one k16 step (4 A + 4 B) into a buffer.
#define LD_KS(BUF, KS, SOFF)                                                  \
    do {                                                                      \
        _Pragma("unroll")                                                     \
        for (int i = 0; i < 4; i++) ldsm4(af[BUF][i], aA[i * 4 + (KS)] + (SOFF)); \
        _Pragma("unroll")                                                     \
        for (int j = 0; j < 4; j++) ldsm4(bf[BUF][j], aB[j * 4 + (KS)] + (SOFF)); \
    } while (0)

// MMAs of one k16 step from a buffer (order identical to prior rounds).
#define MMA_KS(BUF)                                                           \
    do {                                                                      \
        _Pragma("unroll")                                                     \
        for (int i = 0; i < 4; i++)                                           \
            _Pragma("unroll")                                                 \
            for (int j = 0; j < 4; j++) {                                     \
                mma16816(c[i][2 * j],     af[BUF][i], bf[BUF][j][0], bf[BUF][j][2]); \
                mma16816(c[i][2 * j + 1], af[BUF][i], bf[BUF][j][1], bf[BUF][j][3]); \
            }                                                                 \
    } while (0)

// One 64-half chunk: ks pipelined through 2 fragment buffers.
#define COMPUTE_CHUNK(SOFF)                                                   \
    do {                                                                      \
        LD_KS(0, 0, SOFF);                                                    \
        LD_KS(1, 1, SOFF);                                                    \
        MMA_KS(0);                                                            \
        LD_KS(0, 2, SOFF);                                                    \
        MMA_KS(1);                                                            \
        LD_KS(1, 3, SOFF);                                                    \
        MMA_KS(0);                                                            \
        MMA_KS(1);                                                            \
    } while (0)

#define WAIT1 asm volatile("cp.async.wait_group 1;" ::: "memory")
#define WAIT0 asm volatile("cp.async.wait_group 0;" ::: "memory")

__global__ __launch_bounds__(NT, 2) void gemm_scan_kernel(
    const float* __restrict__ b1, const float* __restrict__ beta_p)
{
    extern __shared__ char smem[];
    const uint32_t smem_base = smem_u32_of(smem);
    const int tid  = threadIdx.x;
    const int lane = tid & 31;
    const int wid  = tid >> 5;
    const int wm   = wid >> 1;      // 0..1 : warp row (64 M each)
    const int wn   = wid & 1;       // 0..1 : warp col (64 N each)
    const int bm = blockIdx.y * TIL_M;
    const int bn = blockIdx.x * TIL_N;

    float c[4][8][4];               // warp tile 64x64: 4 m16 x 8 n8 frags
#pragma unroll
    for (int i = 0; i < 4; i++)
#pragma unroll
        for (int j = 0; j < 8; j++)
#pragma unroll
            for (int q = 0; q < 4; q++) c[i][j][q] = 0.0f;

    uint32_t af[2][4][4], bf[2][4][4];   // double-buffered fragments

    // Precompute all swizzled ldsm addresses for stage 0 (32 registers).
    // The swizzle XOR mask depends only on the row (bits >=7 of off), so
    // these are loop-invariant; other stages add a literal offset.
    uint32_t aA[16], aB[16];
    {
        const uint32_t l16 = (uint32_t)((lane >> 4) << 4);
#pragma unroll
        for (int i = 0; i < 4; i++) {
            const uint32_t row = wm * 64 + i * 16 + (lane & 15);
#pragma unroll
            for (int ks = 0; ks < 4; ks++) {
                uint32_t off = row * 128 + ks * 32 + l16;
                off ^= (off >> 3) & 0x70;
                aA[i * 4 + ks] = smem_base + off;
            }
        }
#pragma unroll
        for (int j = 0; j < 4; j++) {
            const uint32_t row = wn * 64 + j * 16 + (lane & 15);
#pragma unroll
            for (int ks = 0; ks < 4; ks++) {
                uint32_t off = row * 128 + ks * 32 + l16;
                off ^= (off >> 3) & 0x70;
                aB[j * 4 + ks] = smem_base + A_STG_BYTES + off;
            }
        }
    }

    // prologue: fill slots 0..1 (depth-2 prefetch)
    load_stage(smem_base, 0, 0, bm, bn, tid);
    cp_commit();
    load_stage(smem_base, 1, 1, bm, bn, tid);
    cp_commit();

    // full-rate phase: kc = 0..20 as 7 groups of 3 (slot = kc % 3 literal)
    for (int g = 0; g < 7; g++) {
        const int kcb = g * 3;
        // kc = kcb, slot 0; prefetch kcb+2 -> slot 2
        WAIT1; __syncthreads();
        load_stage(smem_base, 2, kcb + 2, bm, bn, tid); cp_commit();
        COMPUTE_CHUNK(0);
        // kc = kcb+1, slot 1; prefetch kcb+3 -> slot 0
        WAIT1; __syncthreads();
        load_stage(smem_base, 0, kcb + 3, bm, bn, tid); cp_commit();
        COMPUTE_CHUNK(STAGE_BYTES);
        // kc = kcb+2, slot 2; prefetch kcb+4 -> slot 1
        WAIT1; __syncthreads();
        load_stage(smem_base, 1, kcb + 4, bm, bn, tid); cp_commit();
        COMPUTE_CHUNK(2 * STAGE_BYTES);
    }
    // kc = 21 (slot 0): prefetch 23 -> slot 2
    WAIT1; __syncthreads();
    load_stage(smem_base, 2, 23, bm, bn, tid); cp_commit();
    COMPUTE_CHUNK(0);
    // kc = 22 (slot 1): no prefetch
    WAIT1; __syncthreads();
    COMPUTE_CHUNK(STAGE_BYTES);
    // kc = 23 (slot 2)
    WAIT0; __syncthreads();
    COMPUTE_CHUNK(2 * STAGE_BYTES);

    __syncthreads();   // all compute done before smem is reused as fp32 buffer

    // ------------------ fused epilogue + scan ------------------
    float* sf = reinterpret_cast<float*>(smem);   // [128][129] fp32 = 66KB
#pragma unroll
    for (int i = 0; i < 4; i++) {
        const int r0 = wm * 64 + i * 16 + (lane >> 2);
#pragma unroll
        for (int j = 0; j < 8; j++) {
            const int col = wn * 64 + j * 8 + ((lane & 3) << 1);
            sf[r0 * 129 + col]           = c[i][j][0];
            sf[r0 * 129 + col + 1]       = c[i][j][1];
            sf[(r0 + 8) * 129 + col]     = c[i][j][2];
            sf[(r0 + 8) * 129 + col + 1] = c[i][j][3];
        }
    }
    __syncthreads();

    {
        const float beta_c = fminf(fmaxf(beta_p[0], 0.0f), 1.0f);
        const float bias_h = b1[bn + tid];
        float mem = 0.0f;
#pragma unroll 8
        for (int t = 0; t < TT; t++) {
            const float inp   = sf[t * 129 + tid] + bias_h;
            const float reset = (mem > 1.0f) ? 1.0f : 0.0f;   // THR = 1.0
            mem = fmaf(beta_c, mem, inp - reset);
        }
        g_mem[(size_t)blockIdx.y * HID + bn + tid] = mem;
    }
}

// ---------------------------------------------------------------------------
// Kernel 2 (R10 config — best measured, 12.9us): head GEMM
// out[b][o] = g_mem[b] . Wh[o] + bh[o]; grid (BB, 4), 24 outputs per block.
// ---------------------------------------------------------------------------
__global__ __launch_bounds__(256) void head_kernel(
    const float* __restrict__ Wh, const float* __restrict__ bh,
    float* __restrict__ out)
{
    __shared__ float s_mem[HID];
    const int b  = blockIdx.x;
    const int os = blockIdx.y * 24;           // output range [os, os+24)

    for (int i = threadIdx.x; i < HID; i += 256)
        s_mem[i] = g_mem[(size_t)b * HID + i];
    __syncthreads();

    const int warp = threadIdx.x >> 5;
    const int lane = threadIdx.x & 31;

    for (int o = os + warp; o < os + 24; o += 8) {
        const float4* w = reinterpret_cast<const float4*>(Wh + (size_t)o * HID);
        float acc = 0.0f;
#pragma unroll
        for (int h = lane; h < HID / 4; h += 32) {
            const float4 wv = w[h];
            const float4 mv = *reinterpret_cast<const float4*>(s_mem + h * 4);
            acc = fmaf(wv.x, mv.x, acc);
            acc = fmaf(wv.y, mv.y, acc);
            acc = fmaf(wv.z, mv.z, acc);
            acc = fmaf(wv.w, mv.w, acc);
        }
#pragma unroll
        for (int off = 16; off > 0; off >>= 1)
            acc += __shfl_xor_sync(0xFFFFFFFFu, acc, off);
        if (lane == 0) out[(size_t)b * HOR + o] = acc + bh[o];
    }
}

// ---------------------------------------------------------------------------
extern "C" void kernel_launch(void* const* d_in, const int* in_sizes, int n_in,
                              void* d_out, int out_size)
{
    const float* x    = (const float*)d_in[0];  // [B,T,C]
    const float* W1   = (const float*)d_in[1];  // [HID,C]
    const float* b1   = (const float*)d_in[2];  // [HID]
    const float* Wh   = (const float*)d_in[3];  // [HOR,HID]
    const float* bh   = (const float*)d_in[4];  // [HOR]
    const float* beta = (const float*)d_in[5];  // scalar
    float* out = (float*)d_out;                 // [B,HOR]

    cudaFuncSetAttribute(gemm_scan_kernel,
                         cudaFuncAttributeMaxDynamicSharedMemorySize, SMEM_TOTAL);

    convert_kernel<<<XBLKS + (HID * CC / 4) / 256, 256>>>(x, W1);

    dim3 grid(HID / TIL_N, MM / TIL_M);   // (8, 256) = 2048 CTAs
    gemm_scan_kernel<<<grid, NT, SMEM_TOTAL>>>(b1, beta);

    dim3 hgrid(BB, 4);                    // 1024 blocks
    head_kernel<<<hgrid, 256>>>(Wh, bh, out);
}